// round 1
// baseline (speedup 1.0000x reference)
#include <cuda_runtime.h>
#include <math.h>

#define Bsz 64
#define Hs  512
#define Ss  256
#define Vv  32000

// ------------------- scratch (__device__ globals, no allocation) -------------
__device__ float g_edt[Bsz * Ss];          // encdot stored [b'][s'] : b'*256+s'
__device__ float g_norm[Ss * Bsz];         // normalized [s][b]
__device__ float g_xcat[Bsz * 2048];       // [attn_sum(1024) | input(512) | h0[0](512)]
__device__ float g_xcat1[Bsz * 1024];      // [h1(512) | h0[1](512)]
__device__ float g_gpart[4 * Bsz * 2048];  // split-K partial gates (reused by both layers)
__device__ float g_h2[Bsz * Hs];

// ------------------- attention: encdot[s',b'] = enc[s',b',:] . We ------------
__global__ void k_encdot(const float* __restrict__ enc,
                         const float* __restrict__ attn_W) {
    __shared__ __align__(16) float We[1024];
    for (int i = threadIdx.x; i < 1024; i += blockDim.x) We[i] = attn_W[512 + i];
    __syncthreads();
    int wid  = (blockIdx.x * blockDim.x + threadIdx.x) >> 5;   // 0..16383 = s'*64+b'
    int lane = threadIdx.x & 31;
    const float4* e4 = (const float4*)(enc + (size_t)wid * 1024);
    const float4* w4 = (const float4*)We;
    float acc = 0.f;
#pragma unroll
    for (int it = 0; it < 8; it++) {
        float4 a = e4[it * 32 + lane];
        float4 w = w4[it * 32 + lane];
        acc += a.x * w.x + a.y * w.y + a.z * w.z + a.w * w.w;
    }
#pragma unroll
    for (int o = 16; o; o >>= 1) acc += __shfl_xor_sync(0xFFFFFFFFu, acc, o);
    if (lane == 0) {
        int sp = wid >> 6, bp = wid & 63;
        g_edt[bp * 256 + sp] = acc;
    }
}

// ------------------- softmax over reshape groups -----------------------------
// wt[s,b] = edt[(s&3)*64+b , s>>2]  (hWh + attn_b terms cancel in softmax)
__global__ void k_softmax() {
    int s    = (blockIdx.x * blockDim.x + threadIdx.x) >> 5;   // 0..255
    int lane = threadIdx.x & 31;
    int base = (s >> 2) * 256 + (s & 3) * 64;
    float v0 = g_edt[base + lane];
    float v1 = g_edt[base + 32 + lane];
    float m = fmaxf(v0, v1);
#pragma unroll
    for (int o = 16; o; o >>= 1) m = fmaxf(m, __shfl_xor_sync(0xFFFFFFFFu, m, o));
    float e0 = expf(v0 - m), e1 = expf(v1 - m);
    float sum = e0 + e1;
#pragma unroll
    for (int o = 16; o; o >>= 1) sum += __shfl_xor_sync(0xFFFFFFFFu, sum, o);
    float inv = 1.f / sum;
    g_norm[s * 64 + lane]      = e0 * inv;
    g_norm[s * 64 + 32 + lane] = e1 * inv;
}

// ------------------- attn_sum[b,d] = sum_s norm[s,b]*enc[s,b,d] --------------
__global__ void k_attnsum(const float* __restrict__ enc) {
    int b     = blockIdx.x;        // 0..63
    int chunk = blockIdx.y;        // 0..3
    __shared__ float nc[256];
    nc[threadIdx.x] = g_norm[threadIdx.x * 64 + b];
    __syncthreads();
    int d = chunk * 256 + threadIdx.x;
    const float* ep = enc + b * 1024 + d;
    float a0 = 0.f, a1 = 0.f, a2 = 0.f, a3 = 0.f;
#pragma unroll 4
    for (int s = 0; s < 256; s += 4) {
        a0 += nc[s]     * ep[(s)     * 65536];
        a1 += nc[s + 1] * ep[(s + 1) * 65536];
        a2 += nc[s + 2] * ep[(s + 2) * 65536];
        a3 += nc[s + 3] * ep[(s + 3) * 65536];
    }
    g_xcat[b * 2048 + d] = (a0 + a1) + (a2 + a3);
}

// ------------------- pack input / h0 slices into xcat buffers ----------------
__global__ void k_pack(const float* __restrict__ input, const float* __restrict__ h0) {
    int i = blockIdx.x * blockDim.x + threadIdx.x;   // 0..32767
    int b = i >> 9, j = i & 511;
    g_xcat[b * 2048 + 1024 + j] = input[i];
    g_xcat[b * 2048 + 1536 + j] = h0[i];            // h0[0]
    g_xcat1[b * 1024 + 512 + j] = h0[32768 + i];    // h0[1]
}

// ------------------- generic M=64 GEMM: out = X(64,K) @ [WA|WB]^T + bias -----
// Tile: 64 rows x 32 cols, 256 threads, 4x2 microtile. Split-K via blockIdx.y.
__global__ void k_gemm64(const float* __restrict__ X, int K,
                         const float* __restrict__ WA, int KA,
                         const float* __restrict__ WB,
                         const float* __restrict__ bias0,
                         const float* __restrict__ bias1,
                         float* __restrict__ out, int N, int kChunk) {
    __shared__ float Xs[64][65];
    __shared__ float Ws[32][65];
    int j0   = blockIdx.x * 32;
    int kidx = blockIdx.y;
    int kbeg = kidx * kChunk;
    int kend = kbeg + kChunk;
    int tid  = threadIdx.x;
    int tx   = tid & 15;     // column (and column+16)
    int ty   = tid >> 4;     // 0..15 -> rows ty+16r
    int KB   = K - KA;
    float acc[4][2] = {};

    for (int k0 = kbeg; k0 < kend; k0 += 64) {
        {   // load X tile 64x64
            int kk = tid & 63, r0 = tid >> 6;  // r0: 0..3
            const float* xp = X + k0 + kk;
#pragma unroll
            for (int i = 0; i < 16; i++)
                Xs[r0 + 4 * i][kk] = xp[(r0 + 4 * i) * K];
        }
        {   // load W tile 32x64 (choose WA or WB: chunk never straddles KA)
            int kk = tid & 63, g0 = tid >> 6;
            const float* wp; int ld, kc;
            if (k0 < KA) { wp = WA; ld = KA; kc = k0; }
            else         { wp = WB; ld = KB; kc = k0 - KA; }
#pragma unroll
            for (int i = 0; i < 8; i++)
                Ws[g0 + 4 * i][kk] = wp[(size_t)(j0 + g0 + 4 * i) * ld + kc + kk];
        }
        __syncthreads();
#pragma unroll 16
        for (int k = 0; k < 64; k++) {
            float w0 = Ws[tx][k], w1 = Ws[tx + 16][k];
#pragma unroll
            for (int r = 0; r < 4; r++) {
                float xv = Xs[ty + 16 * r][k];
                acc[r][0] += xv * w0;
                acc[r][1] += xv * w1;
            }
        }
        __syncthreads();
    }

    float b0 = 0.f, b1 = 0.f;
    if (kidx == 0) {
        if (bias0) { b0 += bias0[j0 + tx]; b1 += bias0[j0 + tx + 16]; }
        if (bias1) { b0 += bias1[j0 + tx]; b1 += bias1[j0 + tx + 16]; }
    }
    float* op = out + (size_t)kidx * 64 * N;
#pragma unroll
    for (int r = 0; r < 4; r++) {
        int row = ty + 16 * r;
        op[row * N + j0 + tx]      = acc[r][0] + b0;
        op[row * N + j0 + tx + 16] = acc[r][1] + b1;
    }
}

// ------------------- LSTM cell epilogues (sum split-K parts) -----------------
__device__ __forceinline__ float sigf(float x) { return 1.f / (1.f + expf(-x)); }

__global__ void k_cell0(const float* __restrict__ c0,      // c0[0]
                        float* __restrict__ h_out,          // d_out + 32768 (h_new[0])
                        float* __restrict__ c_out) {        // d_out + 98304 (c_new[0])
    int idx = blockIdx.x * blockDim.x + threadIdx.x;        // 0..32767
    int b = idx >> 9, j = idx & 511;
    int base = b * 2048;
    float gi = 0, gf = 0, gg = 0, go = 0;
#pragma unroll
    for (int p = 0; p < 4; p++) {
        const float* gp = g_gpart + p * 64 * 2048 + base;
        gi += gp[j]; gf += gp[512 + j]; gg += gp[1024 + j]; go += gp[1536 + j];
    }
    float c = sigf(gf) * c0[idx] + sigf(gi) * tanhf(gg);
    float h = sigf(go) * tanhf(c);
    h_out[idx] = h;
    c_out[idx] = c;
    g_xcat1[b * 1024 + j] = h;   // layer-1 input
}

__global__ void k_cell1(const float* __restrict__ c0b,      // c0[1]
                        float* __restrict__ out0,           // d_out (output = h2)
                        float* __restrict__ h_out,          // d_out + 65536 (h_new[1])
                        float* __restrict__ c_out) {        // d_out + 131072 (c_new[1])
    int idx = blockIdx.x * blockDim.x + threadIdx.x;
    int b = idx >> 9, j = idx & 511;
    int base = b * 2048;
    float gi = 0, gf = 0, gg = 0, go = 0;
#pragma unroll
    for (int p = 0; p < 4; p++) {
        const float* gp = g_gpart + p * 64 * 2048 + base;
        gi += gp[j]; gf += gp[512 + j]; gg += gp[1024 + j]; go += gp[1536 + j];
    }
    float c = sigf(gf) * c0b[idx] + sigf(gi) * tanhf(gg);
    float h = sigf(go) * tanhf(c);
    out0[idx]  = h;
    h_out[idx] = h;
    c_out[idx] = c;
    g_h2[idx]  = h;
}

// ------------------- launch ---------------------------------------------------
extern "C" void kernel_launch(void* const* d_in, const int* in_sizes, int n_in,
                              void* d_out, int out_size) {
    const float* input = (const float*)d_in[0];
    const float* h0    = (const float*)d_in[1];
    const float* c0    = (const float*)d_in[2];
    const float* enc   = (const float*)d_in[3];
    const float* attnW = (const float*)d_in[4];
    // d_in[5] = attn_b (cancels in softmax; hWh term also cancels)
    const float* w_ih0 = (const float*)d_in[6];
    const float* w_hh0 = (const float*)d_in[7];
    const float* b_ih0 = (const float*)d_in[8];
    const float* b_hh0 = (const float*)d_in[9];
    const float* w_ih1 = (const float*)d_in[10];
    const float* w_hh1 = (const float*)d_in[11];
    const float* b_ih1 = (const float*)d_in[12];
    const float* b_hh1 = (const float*)d_in[13];
    const float* out_W = (const float*)d_in[14];
    const float* out_b = (const float*)d_in[15];
    float* out = (float*)d_out;

    float *p_xcat, *p_xcat1, *p_gpart, *p_h2;
    cudaGetSymbolAddress((void**)&p_xcat,  g_xcat);
    cudaGetSymbolAddress((void**)&p_xcat1, g_xcat1);
    cudaGetSymbolAddress((void**)&p_gpart, g_gpart);
    cudaGetSymbolAddress((void**)&p_h2,    g_h2);

    // Output layout: [output(32768) | h_new(65536) | c_new(65536) | pred(2048000)]
    float* o_output = out;
    float* o_h1 = out + 32768;
    float* o_h2 = out + 65536;
    float* o_c1 = out + 98304;
    float* o_c2 = out + 131072;
    float* o_pred = out + 163840;

    k_encdot<<<2048, 256>>>(enc, attnW);
    k_softmax<<<32, 256>>>();
    k_pack<<<128, 256>>>(input, h0);
    k_attnsum<<<dim3(64, 4), 256>>>(enc);

    // layer 0 gates: xcat(64,2048) @ [w_ih0 | w_hh0]^T, split-K x4
    k_gemm64<<<dim3(64, 4), 256>>>(p_xcat, 2048, w_ih0, 1536, w_hh0,
                                   b_ih0, b_hh0, p_gpart, 2048, 512);
    k_cell0<<<128, 256>>>(c0, o_h1, o_c1);

    // layer 1 gates: xcat1(64,1024) @ [w_ih1 | w_hh1]^T, split-K x4
    k_gemm64<<<dim3(64, 4), 256>>>(p_xcat1, 1024, w_ih1, 512, w_hh1,
                                   b_ih1, b_hh1, p_gpart, 2048, 256);
    k_cell1<<<128, 256>>>(c0 + 32768, o_output, o_h2, o_c2);

    // pred: h2(64,512) @ out_W^T + out_b  -> (64, 32000)
    k_gemm64<<<dim3(1000, 1), 256>>>(p_h2, 512, out_W, 512, nullptr,
                                     out_b, nullptr, o_pred, 32000, 512);
}

// round 3
// speedup vs baseline: 1.3112x; 1.3112x over previous
#include <cuda_runtime.h>
#include <cuda_bf16.h>
#include <math.h>

#define Bsz 64
#define Hs  512
#define Ss  256
#define Vv  32000

// ------------------- scratch (__device__ globals, no allocation) -------------
__device__ float g_edt[Bsz * Ss];            // encdot [b'][s']
__device__ float g_norm[Ss * Bsz];           // normalized [s][b]
__device__ float g_gpart[4 * Bsz * 2048];    // split-K partial gates
// bf16 hi/lo activation buffers (GEMM A operands)
__device__ __nv_bfloat16 g_Ah0[Bsz * 2048], g_Al0[Bsz * 2048];  // xcat layer0
__device__ __nv_bfloat16 g_Ah1[Bsz * 1024], g_Al1[Bsz * 1024];  // xcat layer1
__device__ __nv_bfloat16 g_Ah2[Bsz * 512],  g_Al2[Bsz * 512];   // h2

__device__ __forceinline__ void bfsplit(float x, __nv_bfloat16& h, __nv_bfloat16& l) {
    h = __float2bfloat16(x);
    l = __float2bfloat16(x - __bfloat162float(h));
}

// ------------------- attention: encdot[s',b'] = enc[s',b',:] . We ------------
__global__ void k_encdot(const float* __restrict__ enc,
                         const float* __restrict__ attn_W) {
    __shared__ __align__(16) float We[1024];
    for (int i = threadIdx.x; i < 1024; i += blockDim.x) We[i] = attn_W[512 + i];
    __syncthreads();
    int wid  = (blockIdx.x * blockDim.x + threadIdx.x) >> 5;
    int lane = threadIdx.x & 31;
    const float4* e4 = (const float4*)(enc + (size_t)wid * 1024);
    const float4* w4 = (const float4*)We;
    float acc = 0.f;
#pragma unroll
    for (int it = 0; it < 8; it++) {
        float4 a = e4[it * 32 + lane];
        float4 w = w4[it * 32 + lane];
        acc += a.x * w.x + a.y * w.y + a.z * w.z + a.w * w.w;
    }
#pragma unroll
    for (int o = 16; o; o >>= 1) acc += __shfl_xor_sync(0xFFFFFFFFu, acc, o);
    if (lane == 0) {
        int sp = wid >> 6, bp = wid & 63;
        g_edt[bp * 256 + sp] = acc;
    }
}

// ------------------- softmax (hWh + attn_b cancel within rows) ---------------
__global__ void k_softmax() {
    int s    = (blockIdx.x * blockDim.x + threadIdx.x) >> 5;
    int lane = threadIdx.x & 31;
    int base = (s >> 2) * 256 + (s & 3) * 64;
    float v0 = g_edt[base + lane];
    float v1 = g_edt[base + 32 + lane];
    float m = fmaxf(v0, v1);
#pragma unroll
    for (int o = 16; o; o >>= 1) m = fmaxf(m, __shfl_xor_sync(0xFFFFFFFFu, m, o));
    float e0 = expf(v0 - m), e1 = expf(v1 - m);
    float sum = e0 + e1;
#pragma unroll
    for (int o = 16; o; o >>= 1) sum += __shfl_xor_sync(0xFFFFFFFFu, sum, o);
    float inv = 1.f / sum;
    g_norm[s * 64 + lane]      = e0 * inv;
    g_norm[s * 64 + 32 + lane] = e1 * inv;
}

// ------------------- attn_sum -> xcat[:,0:1024] as bf16 hi/lo ----------------
__global__ void k_attnsum(const float* __restrict__ enc) {
    int b     = blockIdx.x;
    int chunk = blockIdx.y;
    __shared__ float nc[256];
    nc[threadIdx.x] = g_norm[threadIdx.x * 64 + b];
    __syncthreads();
    int d = chunk * 256 + threadIdx.x;
    const float* ep = enc + b * 1024 + d;
    float a0 = 0.f, a1 = 0.f, a2 = 0.f, a3 = 0.f;
#pragma unroll 4
    for (int s = 0; s < 256; s += 4) {
        a0 += nc[s]     * ep[(s)     * 65536];
        a1 += nc[s + 1] * ep[(s + 1) * 65536];
        a2 += nc[s + 2] * ep[(s + 2) * 65536];
        a3 += nc[s + 3] * ep[(s + 3) * 65536];
    }
    float v = (a0 + a1) + (a2 + a3);
    __nv_bfloat16 h, l; bfsplit(v, h, l);
    g_Ah0[b * 2048 + d] = h;
    g_Al0[b * 2048 + d] = l;
}

// ------------------- pack input / h0 slices (as hi/lo) -----------------------
__global__ void k_pack(const float* __restrict__ input, const float* __restrict__ h0) {
    int i = blockIdx.x * blockDim.x + threadIdx.x;   // 0..32767
    int b = i >> 9, j = i & 511;
    __nv_bfloat16 h, l;
    bfsplit(input[i], h, l);
    g_Ah0[b * 2048 + 1024 + j] = h; g_Al0[b * 2048 + 1024 + j] = l;
    bfsplit(h0[i], h, l);
    g_Ah0[b * 2048 + 1536 + j] = h; g_Al0[b * 2048 + 1536 + j] = l;
    bfsplit(h0[32768 + i], h, l);
    g_Ah1[b * 1024 + 512 + j] = h;  g_Al1[b * 1024 + 512 + j] = l;
}

// ------------------- tensor-core GEMM: out = A(64,K) @ [WA|WB]^T + bias ------
// bf16-split (hi/lo) mma.m16n8k16, fp32 accumulate. Block: 128 thr, tile 64x64.
// Split-K via blockIdx.y (kChunk multiple of 32; chunks never straddle KA).
__device__ __forceinline__ void ldmx4(unsigned* r, unsigned addr) {
    asm volatile("ldmatrix.sync.aligned.m8n8.x4.shared.b16 {%0,%1,%2,%3}, [%4];"
                 : "=r"(r[0]), "=r"(r[1]), "=r"(r[2]), "=r"(r[3]) : "r"(addr));
}
__device__ __forceinline__ void mma16816(float* d, const unsigned* a, const unsigned* b) {
    asm volatile("mma.sync.aligned.m16n8k16.row.col.f32.bf16.bf16.f32 "
                 "{%0,%1,%2,%3},{%4,%5,%6,%7},{%8,%9},{%0,%1,%2,%3};"
                 : "+f"(d[0]), "+f"(d[1]), "+f"(d[2]), "+f"(d[3])
                 : "r"(a[0]), "r"(a[1]), "r"(a[2]), "r"(a[3]), "r"(b[0]), "r"(b[1]));
}

__global__ void __launch_bounds__(128) tc_gemm(
    const __nv_bfloat16* __restrict__ Ah, const __nv_bfloat16* __restrict__ Al, int K,
    const float* __restrict__ WA, int KA, const float* __restrict__ WB,
    const float* __restrict__ bias0, const float* __restrict__ bias1,
    float* __restrict__ out, int N, int kChunk)
{
    __shared__ __align__(16) __nv_bfloat16 sAh[64 * 40], sAl[64 * 40];
    __shared__ __align__(16) __nv_bfloat16 sBh[64 * 40], sBl[64 * 40];
    int tid = threadIdx.x, warp = tid >> 5, lane = tid & 31;
    int j0   = blockIdx.x * 64;
    int kidx = blockIdx.y;
    int kbeg = kidx * kChunk, kend = kbeg + kChunk;
    int KB = K - KA;
    float acc[4][2][4] = {};

    // ldmatrix lane->address components
    int a_row = lane & 15;
    int a_k   = (lane >> 4) * 8;
    int b_row = warp * 16 + ((lane >> 4) << 3) + (lane & 7);
    int b_k   = ((lane >> 3) & 1) * 8;

    unsigned sAh_b = (unsigned)__cvta_generic_to_shared(sAh);
    unsigned sAl_b = (unsigned)__cvta_generic_to_shared(sAl);
    unsigned sBh_b = (unsigned)__cvta_generic_to_shared(sBh);
    unsigned sBl_b = (unsigned)__cvta_generic_to_shared(sBl);

    for (int k0 = kbeg; k0 < kend; k0 += 32) {
        // A chunk 64x32 bf16 (hi + lo), vectorized uint4 copies
#pragma unroll
        for (int i = 0; i < 2; i++) {
            int idx = i * 128 + tid;         // 0..255 uint4
            int row = idx >> 2, c8 = idx & 3;
            size_t goff = (size_t)row * K + k0 + c8 * 8;
            *(uint4*)((char*)sAh + row * 80 + c8 * 16) = *(const uint4*)(Ah + goff);
            *(uint4*)((char*)sAl + row * 80 + c8 * 16) = *(const uint4*)(Al + goff);
        }
        // W chunk 64x32 fp32 -> split to bf16 hi/lo in smem
        {
            const float* wp; int ld, kc;
            if (k0 < KA) { wp = WA; ld = KA; kc = k0; }
            else         { wp = WB; ld = KB; kc = k0 - KA; }
#pragma unroll
            for (int i = 0; i < 4; i++) {
                int idx = i * 128 + tid;     // 0..511 float4
                int row = idx >> 3, c4 = idx & 7;
                float4 v = *(const float4*)(wp + (size_t)(j0 + row) * ld + kc + c4 * 4);
                __nv_bfloat16 hx, lx, hy, ly, hz, lz, hw, lw;
                bfsplit(v.x, hx, lx); bfsplit(v.y, hy, ly);
                bfsplit(v.z, hz, lz); bfsplit(v.w, hw, lw);
                __nv_bfloat162 H0; H0.x = hx; H0.y = hy;
                __nv_bfloat162 H1; H1.x = hz; H1.y = hw;
                __nv_bfloat162 L0; L0.x = lx; L0.y = ly;
                __nv_bfloat162 L1; L1.x = lz; L1.y = lw;
                char* bh = (char*)sBh + row * 80 + c4 * 8;
                char* bl = (char*)sBl + row * 80 + c4 * 8;
                *(__nv_bfloat162*)bh = H0; *(__nv_bfloat162*)(bh + 4) = H1;
                *(__nv_bfloat162*)bl = L0; *(__nv_bfloat162*)(bl + 4) = L1;
            }
        }
        __syncthreads();
#pragma unroll
        for (int kk = 0; kk < 32; kk += 16) {
            unsigned bh[4], bl[4];
            unsigned baddr = (unsigned)(b_row * 80 + (kk + b_k) * 2);
            ldmx4(bh, sBh_b + baddr);
            ldmx4(bl, sBl_b + baddr);
#pragma unroll
            for (int mi = 0; mi < 4; mi++) {
                unsigned ah[4], al[4];
                unsigned aaddr = (unsigned)((mi * 16 + a_row) * 80 + (kk + a_k) * 2);
                ldmx4(ah, sAh_b + aaddr);
                ldmx4(al, sAl_b + aaddr);
                mma16816(acc[mi][0], ah, &bh[0]);
                mma16816(acc[mi][0], ah, &bl[0]);
                mma16816(acc[mi][0], al, &bh[0]);
                mma16816(acc[mi][1], ah, &bh[2]);
                mma16816(acc[mi][1], ah, &bl[2]);
                mma16816(acc[mi][1], al, &bh[2]);
            }
        }
        __syncthreads();
    }

    int orow = lane >> 2;
    int ocol = (lane & 3) * 2;
    float* op = out + (size_t)kidx * 64 * N;
#pragma unroll
    for (int mi = 0; mi < 4; mi++) {
#pragma unroll
        for (int ni = 0; ni < 2; ni++) {
            int col = j0 + warp * 16 + ni * 8 + ocol;
            float bA = 0.f, bB = 0.f;
            if (kidx == 0) {
                if (bias0) { bA += bias0[col]; bB += bias0[col + 1]; }
                if (bias1) { bA += bias1[col]; bB += bias1[col + 1]; }
            }
            int r0 = mi * 16 + orow;
            op[(size_t)r0 * N + col]           = acc[mi][ni][0] + bA;
            op[(size_t)r0 * N + col + 1]       = acc[mi][ni][1] + bB;
            op[(size_t)(r0 + 8) * N + col]     = acc[mi][ni][2] + bA;
            op[(size_t)(r0 + 8) * N + col + 1] = acc[mi][ni][3] + bB;
        }
    }
}

// ------------------- LSTM cell epilogues (sum split-K parts) -----------------
__device__ __forceinline__ float sigf(float x) { return 1.f / (1.f + expf(-x)); }

__global__ void k_cell0(const float* __restrict__ c0,
                        float* __restrict__ h_out,
                        float* __restrict__ c_out) {
    int idx = blockIdx.x * blockDim.x + threadIdx.x;
    int b = idx >> 9, j = idx & 511;
    int base = b * 2048;
    float gi = 0, gf = 0, gg = 0, go = 0;
#pragma unroll
    for (int p = 0; p < 4; p++) {
        const float* gp = g_gpart + p * 64 * 2048 + base;
        gi += gp[j]; gf += gp[512 + j]; gg += gp[1024 + j]; go += gp[1536 + j];
    }
    float c = sigf(gf) * c0[idx] + sigf(gi) * tanhf(gg);
    float h = sigf(go) * tanhf(c);
    h_out[idx] = h;
    c_out[idx] = c;
    __nv_bfloat16 hh, ll; bfsplit(h, hh, ll);
    g_Ah1[b * 1024 + j] = hh;
    g_Al1[b * 1024 + j] = ll;
}

__global__ void k_cell1(const float* __restrict__ c0b,
                        float* __restrict__ out0,
                        float* __restrict__ h_out,
                        float* __restrict__ c_out) {
    int idx = blockIdx.x * blockDim.x + threadIdx.x;
    int b = idx >> 9, j = idx & 511;
    int base = b * 2048;
    float gi = 0, gf = 0, gg = 0, go = 0;
#pragma unroll
    for (int p = 0; p < 4; p++) {
        const float* gp = g_gpart + p * 64 * 2048 + base;
        gi += gp[j]; gf += gp[512 + j]; gg += gp[1024 + j]; go += gp[1536 + j];
    }
    float c = sigf(gf) * c0b[idx] + sigf(gi) * tanhf(gg);
    float h = sigf(go) * tanhf(c);
    out0[idx]  = h;
    h_out[idx] = h;
    c_out[idx] = c;
    __nv_bfloat16 hh, ll; bfsplit(h, hh, ll);
    g_Ah2[idx] = hh;
    g_Al2[idx] = ll;
}

// ------------------- launch ---------------------------------------------------
extern "C" void kernel_launch(void* const* d_in, const int* in_sizes, int n_in,
                              void* d_out, int out_size) {
    const float* input = (const float*)d_in[0];
    const float* h0    = (const float*)d_in[1];
    const float* c0    = (const float*)d_in[2];
    const float* enc   = (const float*)d_in[3];
    const float* attnW = (const float*)d_in[4];
    const float* w_ih0 = (const float*)d_in[6];
    const float* w_hh0 = (const float*)d_in[7];
    const float* b_ih0 = (const float*)d_in[8];
    const float* b_hh0 = (const float*)d_in[9];
    const float* w_ih1 = (const float*)d_in[10];
    const float* w_hh1 = (const float*)d_in[11];
    const float* b_ih1 = (const float*)d_in[12];
    const float* b_hh1 = (const float*)d_in[13];
    const float* out_W = (const float*)d_in[14];
    const float* out_b = (const float*)d_in[15];
    float* out = (float*)d_out;

    float* p_gpart;
    __nv_bfloat16 *p_Ah0, *p_Al0, *p_Ah1, *p_Al1, *p_Ah2, *p_Al2;
    cudaGetSymbolAddress((void**)&p_gpart, g_gpart);
    cudaGetSymbolAddress((void**)&p_Ah0, g_Ah0);
    cudaGetSymbolAddress((void**)&p_Al0, g_Al0);
    cudaGetSymbolAddress((void**)&p_Ah1, g_Ah1);
    cudaGetSymbolAddress((void**)&p_Al1, g_Al1);
    cudaGetSymbolAddress((void**)&p_Ah2, g_Ah2);
    cudaGetSymbolAddress((void**)&p_Al2, g_Al2);

    // Output layout: [output | h_new | c_new | pred]
    float* o_output = out;
    float* o_h1 = out + 32768;
    float* o_h2 = out + 65536;
    float* o_c1 = out + 98304;
    float* o_c2 = out + 131072;
    float* o_pred = out + 163840;

    k_encdot<<<2048, 256>>>(enc, attnW);
    k_softmax<<<32, 256>>>();
    k_pack<<<128, 256>>>(input, h0);
    k_attnsum<<<dim3(64, 4), 256>>>(enc);

    // layer 0 gates: (64,2048) @ [w_ih0|w_hh0]^T, split-K x4
    tc_gemm<<<dim3(32, 4), 128>>>(p_Ah0, p_Al0, 2048, w_ih0, 1536, w_hh0,
                                  b_ih0, b_hh0, p_gpart, 2048, 512);
    k_cell0<<<128, 256>>>(c0, o_h1, o_c1);

    // layer 1 gates: (64,1024) @ [w_ih1|w_hh1]^T, split-K x4
    tc_gemm<<<dim3(32, 4), 128>>>(p_Ah1, p_Al1, 1024, w_ih1, 512, w_hh1,
                                  b_ih1, b_hh1, p_gpart, 2048, 256);
    k_cell1<<<128, 256>>>(c0 + 32768, o_output, o_h2, o_c2);

    // pred: (64,512) @ out_W^T + out_b -> (64, 32000)
    tc_gemm<<<dim3(500, 1), 128>>>(p_Ah2, p_Al2, 512, out_W, 512, nullptr,
                                   out_b, nullptr, o_pred, 32000, 512);
}

// round 4
// speedup vs baseline: 2.2371x; 1.7061x over previous
#include <cuda_runtime.h>
#include <cuda_bf16.h>
#include <math.h>

#define Bsz 64
#define Hs  512
#define Ss  256
#define Vv  32000

// ------------------- scratch (__device__ globals, no allocation) -------------
__device__ float g_edt[Bsz * Ss];            // encdot [b'][s']
__device__ float g_norm[Ss * Bsz];           // normalized [s][b]
__device__ float g_aspart[4 * Bsz * 1024];   // attn_sum split-S partials [sp][b][d]
__device__ float g_gpart[4 * Bsz * 2048];    // split-K partial gates
// bf16 hi/lo activation buffers (GEMM A operands)
__device__ __nv_bfloat16 g_Ah0[Bsz * 2048], g_Al0[Bsz * 2048];  // xcat layer0
__device__ __nv_bfloat16 g_Ah1[Bsz * 1024], g_Al1[Bsz * 1024];  // xcat layer1
__device__ __nv_bfloat16 g_Ah2[Bsz * 512],  g_Al2[Bsz * 512];   // h2

__device__ __forceinline__ void bfsplit(float x, __nv_bfloat16& h, __nv_bfloat16& l) {
    h = __float2bfloat16(x);
    l = __float2bfloat16(x - __bfloat162float(h));
}

// ------------------- attention: encdot[s',b'] = enc[s',b',:] . We ------------
__global__ void k_encdot(const float* __restrict__ enc,
                         const float* __restrict__ attn_W) {
    __shared__ __align__(16) float We[1024];
    for (int i = threadIdx.x; i < 1024; i += blockDim.x) We[i] = attn_W[512 + i];
    __syncthreads();
    int wid  = (blockIdx.x * blockDim.x + threadIdx.x) >> 5;
    int lane = threadIdx.x & 31;
    const float4* e4 = (const float4*)(enc + (size_t)wid * 1024);
    const float4* w4 = (const float4*)We;
    float acc = 0.f;
#pragma unroll
    for (int it = 0; it < 8; it++) {
        float4 a = e4[it * 32 + lane];
        float4 w = w4[it * 32 + lane];
        acc += a.x * w.x + a.y * w.y + a.z * w.z + a.w * w.w;
    }
#pragma unroll
    for (int o = 16; o; o >>= 1) acc += __shfl_xor_sync(0xFFFFFFFFu, acc, o);
    if (lane == 0) {
        int sp = wid >> 6, bp = wid & 63;
        g_edt[bp * 256 + sp] = acc;
    }
}

// ------------------- fused softmax + pack ------------------------------------
// blocks 0..31: softmax (hWh + attn_b cancel). blocks 32..159: pack input/h0.
__global__ void k_softpack(const float* __restrict__ input,
                           const float* __restrict__ h0) {
    if (blockIdx.x < 32) {
        int s    = (blockIdx.x * blockDim.x + threadIdx.x) >> 5;
        int lane = threadIdx.x & 31;
        int base = (s >> 2) * 256 + (s & 3) * 64;
        float v0 = g_edt[base + lane];
        float v1 = g_edt[base + 32 + lane];
        float m = fmaxf(v0, v1);
#pragma unroll
        for (int o = 16; o; o >>= 1) m = fmaxf(m, __shfl_xor_sync(0xFFFFFFFFu, m, o));
        float e0 = expf(v0 - m), e1 = expf(v1 - m);
        float sum = e0 + e1;
#pragma unroll
        for (int o = 16; o; o >>= 1) sum += __shfl_xor_sync(0xFFFFFFFFu, sum, o);
        float inv = 1.f / sum;
        g_norm[s * 64 + lane]      = e0 * inv;
        g_norm[s * 64 + 32 + lane] = e1 * inv;
    } else {
        int i = (blockIdx.x - 32) * blockDim.x + threadIdx.x;   // 0..32767
        int b = i >> 9, j = i & 511;
        __nv_bfloat16 h, l;
        bfsplit(input[i], h, l);
        g_Ah0[b * 2048 + 1024 + j] = h; g_Al0[b * 2048 + 1024 + j] = l;
        bfsplit(h0[i], h, l);
        g_Ah0[b * 2048 + 1536 + j] = h; g_Al0[b * 2048 + 1536 + j] = l;
        bfsplit(h0[32768 + i], h, l);
        g_Ah1[b * 1024 + 512 + j] = h;  g_Al1[b * 1024 + 512 + j] = l;
    }
}

// ------------------- attn_sum split-S partials -------------------------------
__global__ void k_attnsum(const float* __restrict__ enc) {
    int b     = blockIdx.x;        // 0..63
    int chunk = blockIdx.y;        // 0..3
    int sp    = blockIdx.z;        // 0..3 (S split)
    __shared__ float nc[64];
    if (threadIdx.x < 64)
        nc[threadIdx.x] = g_norm[(sp * 64 + threadIdx.x) * 64 + b];
    __syncthreads();
    int d = chunk * 256 + threadIdx.x;
    const float* ep = enc + (size_t)sp * 64 * 65536 + b * 1024 + d;
    float a0 = 0.f, a1 = 0.f, a2 = 0.f, a3 = 0.f;
#pragma unroll 4
    for (int s = 0; s < 64; s += 4) {
        a0 += nc[s]     * ep[(s)     * 65536];
        a1 += nc[s + 1] * ep[(s + 1) * 65536];
        a2 += nc[s + 2] * ep[(s + 2) * 65536];
        a3 += nc[s + 3] * ep[(s + 3) * 65536];
    }
    g_aspart[(sp * 64 + b) * 1024 + d] = (a0 + a1) + (a2 + a3);
}

// ------------------- reduce partials -> xcat[:,0:1024] hi/lo -----------------
__global__ void k_asreduce() {
    int idx = blockIdx.x * blockDim.x + threadIdx.x;   // 0..65535
    int b = idx >> 10, d = idx & 1023;
    float v = g_aspart[b * 1024 + d] + g_aspart[(64 + b) * 1024 + d]
            + g_aspart[(128 + b) * 1024 + d] + g_aspart[(192 + b) * 1024 + d];
    __nv_bfloat16 h, l; bfsplit(v, h, l);
    g_Ah0[b * 2048 + d] = h;
    g_Al0[b * 2048 + d] = l;
}

// ------------------- tensor-core GEMM: out = A(64,K) @ [WA|WB]^T + bias ------
// bf16-split (hi/lo) mma.m16n8k16, fp32 accumulate. 256 threads, tile 64x64,
// warps 2(M)x4(N). Register-staged pipeline hides global load latency.
// Split-K via blockIdx.y (kChunk multiple of 32; chunks never straddle KA).
__device__ __forceinline__ void ldmx4(unsigned* r, unsigned addr) {
    asm volatile("ldmatrix.sync.aligned.m8n8.x4.shared.b16 {%0,%1,%2,%3}, [%4];"
                 : "=r"(r[0]), "=r"(r[1]), "=r"(r[2]), "=r"(r[3]) : "r"(addr));
}
__device__ __forceinline__ void mma16816(float* d, const unsigned* a, const unsigned* b) {
    asm volatile("mma.sync.aligned.m16n8k16.row.col.f32.bf16.bf16.f32 "
                 "{%0,%1,%2,%3},{%4,%5,%6,%7},{%8,%9},{%0,%1,%2,%3};"
                 : "+f"(d[0]), "+f"(d[1]), "+f"(d[2]), "+f"(d[3])
                 : "r"(a[0]), "r"(a[1]), "r"(a[2]), "r"(a[3]), "r"(b[0]), "r"(b[1]));
}

__global__ void __launch_bounds__(256) tc_gemm(
    const __nv_bfloat16* __restrict__ Ah, const __nv_bfloat16* __restrict__ Al, int K,
    const float* __restrict__ WA, int KA, const float* __restrict__ WB,
    const float* __restrict__ bias0, const float* __restrict__ bias1,
    float* __restrict__ out, int N, int kChunk)
{
    __shared__ __align__(16) __nv_bfloat16 sAh[64 * 40], sAl[64 * 40];
    __shared__ __align__(16) __nv_bfloat16 sBh[64 * 40], sBl[64 * 40];
    int tid = threadIdx.x, warp = tid >> 5, lane = tid & 31;
    int warp_m = warp >> 2, warp_n = warp & 3;
    int j0   = blockIdx.x * 64;
    int kidx = blockIdx.y;
    int kbeg = kidx * kChunk, kend = kbeg + kChunk;
    int KB = K - KA;
    float acc[2][2][4] = {};

    // ldmatrix lane->address components
    int a_row = lane & 15;
    int a_k   = (lane >> 4) * 8;
    int b_row = warp_n * 16 + ((lane >> 4) << 3) + (lane & 7);
    int b_k   = ((lane >> 3) & 1) * 8;

    unsigned sAh_b = (unsigned)__cvta_generic_to_shared(sAh);
    unsigned sAl_b = (unsigned)__cvta_generic_to_shared(sAl);
    unsigned sBh_b = (unsigned)__cvta_generic_to_shared(sBh);
    unsigned sBl_b = (unsigned)__cvta_generic_to_shared(sBl);

    // load-index precompute
    int arow = tid >> 2, ac8 = tid & 3;            // A: 64 rows x 4 uint4
    int wrow = tid >> 3, wc4 = tid & 7;            // W: 32 rows x 8 float4 (x2)

    // staging registers
    uint4 rAh, rAl; float4 rW0, rW1;

    auto loadregs = [&](int k0) {
        rAh = *(const uint4*)(Ah + (size_t)arow * K + k0 + ac8 * 8);
        rAl = *(const uint4*)(Al + (size_t)arow * K + k0 + ac8 * 8);
        const float* wp; int ld, kc;
        if (k0 < KA) { wp = WA; ld = KA; kc = k0; }
        else         { wp = WB; ld = KB; kc = k0 - KA; }
        rW0 = *(const float4*)(wp + (size_t)(j0 + wrow) * ld + kc + wc4 * 4);
        rW1 = *(const float4*)(wp + (size_t)(j0 + wrow + 32) * ld + kc + wc4 * 4);
    };
    auto storeregs = [&]() {
        *(uint4*)((char*)sAh + arow * 80 + ac8 * 16) = rAh;
        *(uint4*)((char*)sAl + arow * 80 + ac8 * 16) = rAl;
#pragma unroll
        for (int half = 0; half < 2; half++) {
            float4 v = half ? rW1 : rW0;
            int row = wrow + half * 32;
            __nv_bfloat16 hx, lx, hy, ly, hz, lz, hw, lw;
            bfsplit(v.x, hx, lx); bfsplit(v.y, hy, ly);
            bfsplit(v.z, hz, lz); bfsplit(v.w, hw, lw);
            __nv_bfloat162 H0; H0.x = hx; H0.y = hy;
            __nv_bfloat162 H1; H1.x = hz; H1.y = hw;
            __nv_bfloat162 L0; L0.x = lx; L0.y = ly;
            __nv_bfloat162 L1; L1.x = lz; L1.y = lw;
            char* bh = (char*)sBh + row * 80 + wc4 * 8;
            char* bl = (char*)sBl + row * 80 + wc4 * 8;
            *(__nv_bfloat162*)bh = H0; *(__nv_bfloat162*)(bh + 4) = H1;
            *(__nv_bfloat162*)bl = L0; *(__nv_bfloat162*)(bl + 4) = L1;
        }
    };

    loadregs(kbeg);
    for (int k0 = kbeg; k0 < kend; k0 += 32) {
        storeregs();
        __syncthreads();
        if (k0 + 32 < kend) loadregs(k0 + 32);   // overlap next loads with MMA
#pragma unroll
        for (int kk = 0; kk < 32; kk += 16) {
            unsigned bh[4], bl[4];
            unsigned baddr = (unsigned)(b_row * 80 + (kk + b_k) * 2);
            ldmx4(bh, sBh_b + baddr);
            ldmx4(bl, sBl_b + baddr);
#pragma unroll
            for (int mi = 0; mi < 2; mi++) {
                unsigned ah[4], al[4];
                int grow = warp_m * 32 + mi * 16 + a_row;
                unsigned aaddr = (unsigned)(grow * 80 + (kk + a_k) * 2);
                ldmx4(ah, sAh_b + aaddr);
                ldmx4(al, sAl_b + aaddr);
                mma16816(acc[mi][0], ah, &bh[0]);
                mma16816(acc[mi][0], ah, &bl[0]);
                mma16816(acc[mi][0], al, &bh[0]);
                mma16816(acc[mi][1], ah, &bh[2]);
                mma16816(acc[mi][1], ah, &bl[2]);
                mma16816(acc[mi][1], al, &bh[2]);
            }
        }
        __syncthreads();
    }

    int orow = lane >> 2;
    int ocol = (lane & 3) * 2;
    float* op = out + (size_t)kidx * 64 * N;
#pragma unroll
    for (int mi = 0; mi < 2; mi++) {
#pragma unroll
        for (int nj = 0; nj < 2; nj++) {
            int col = j0 + warp_n * 16 + nj * 8 + ocol;
            float bA = 0.f, bB = 0.f;
            if (kidx == 0) {
                if (bias0) { bA += bias0[col]; bB += bias0[col + 1]; }
                if (bias1) { bA += bias1[col]; bB += bias1[col + 1]; }
            }
            int r0 = warp_m * 32 + mi * 16 + orow;
            op[(size_t)r0 * N + col]           = acc[mi][nj][0] + bA;
            op[(size_t)r0 * N + col + 1]       = acc[mi][nj][1] + bB;
            op[(size_t)(r0 + 8) * N + col]     = acc[mi][nj][2] + bA;
            op[(size_t)(r0 + 8) * N + col + 1] = acc[mi][nj][3] + bB;
        }
    }
}

// ------------------- LSTM cell epilogues (sum split-K parts) -----------------
__device__ __forceinline__ float sigf(float x) { return 1.f / (1.f + expf(-x)); }

__global__ void k_cell0(const float* __restrict__ c0,
                        float* __restrict__ h_out,
                        float* __restrict__ c_out) {
    int idx = blockIdx.x * blockDim.x + threadIdx.x;
    int b = idx >> 9, j = idx & 511;
    int base = b * 2048;
    float gi = 0, gf = 0, gg = 0, go = 0;
#pragma unroll
    for (int p = 0; p < 4; p++) {
        const float* gp = g_gpart + p * 64 * 2048 + base;
        gi += gp[j]; gf += gp[512 + j]; gg += gp[1024 + j]; go += gp[1536 + j];
    }
    float c = sigf(gf) * c0[idx] + sigf(gi) * tanhf(gg);
    float h = sigf(go) * tanhf(c);
    h_out[idx] = h;
    c_out[idx] = c;
    __nv_bfloat16 hh, ll; bfsplit(h, hh, ll);
    g_Ah1[b * 1024 + j] = hh;
    g_Al1[b * 1024 + j] = ll;
}

__global__ void k_cell1(const float* __restrict__ c0b,
                        float* __restrict__ out0,
                        float* __restrict__ h_out,
                        float* __restrict__ c_out) {
    int idx = blockIdx.x * blockDim.x + threadIdx.x;
    int b = idx >> 9, j = idx & 511;
    int base = b * 2048;
    float gi = 0, gf = 0, gg = 0, go = 0;
#pragma unroll
    for (int p = 0; p < 4; p++) {
        const float* gp = g_gpart + p * 64 * 2048 + base;
        gi += gp[j]; gf += gp[512 + j]; gg += gp[1024 + j]; go += gp[1536 + j];
    }
    float c = sigf(gf) * c0b[idx] + sigf(gi) * tanhf(gg);
    float h = sigf(go) * tanhf(c);
    out0[idx]  = h;
    h_out[idx] = h;
    c_out[idx] = c;
    __nv_bfloat16 hh, ll; bfsplit(h, hh, ll);
    g_Ah2[idx] = hh;
    g_Al2[idx] = ll;
}

// ------------------- launch ---------------------------------------------------
extern "C" void kernel_launch(void* const* d_in, const int* in_sizes, int n_in,
                              void* d_out, int out_size) {
    const float* input = (const float*)d_in[0];
    const float* h0    = (const float*)d_in[1];
    const float* c0    = (const float*)d_in[2];
    const float* enc   = (const float*)d_in[3];
    const float* attnW = (const float*)d_in[4];
    const float* w_ih0 = (const float*)d_in[6];
    const float* w_hh0 = (const float*)d_in[7];
    const float* b_ih0 = (const float*)d_in[8];
    const float* b_hh0 = (const float*)d_in[9];
    const float* w_ih1 = (const float*)d_in[10];
    const float* w_hh1 = (const float*)d_in[11];
    const float* b_ih1 = (const float*)d_in[12];
    const float* b_hh1 = (const float*)d_in[13];
    const float* out_W = (const float*)d_in[14];
    const float* out_b = (const float*)d_in[15];
    float* out = (float*)d_out;

    float* p_gpart;
    __nv_bfloat16 *p_Ah0, *p_Al0, *p_Ah1, *p_Al1, *p_Ah2, *p_Al2;
    cudaGetSymbolAddress((void**)&p_gpart, g_gpart);
    cudaGetSymbolAddress((void**)&p_Ah0, g_Ah0);
    cudaGetSymbolAddress((void**)&p_Al0, g_Al0);
    cudaGetSymbolAddress((void**)&p_Ah1, g_Ah1);
    cudaGetSymbolAddress((void**)&p_Al1, g_Al1);
    cudaGetSymbolAddress((void**)&p_Ah2, g_Ah2);
    cudaGetSymbolAddress((void**)&p_Al2, g_Al2);

    // Output layout: [output | h_new | c_new | pred]
    float* o_output = out;
    float* o_h1 = out + 32768;
    float* o_h2 = out + 65536;
    float* o_c1 = out + 98304;
    float* o_c2 = out + 131072;
    float* o_pred = out + 163840;

    k_encdot<<<2048, 256>>>(enc, attnW);
    k_softpack<<<160, 256>>>(input, h0);
    k_attnsum<<<dim3(64, 4, 4), 256>>>(enc);
    k_asreduce<<<256, 256>>>();

    // layer 0 gates: (64,2048) @ [w_ih0|w_hh0]^T, split-K x4
    tc_gemm<<<dim3(32, 4), 256>>>(p_Ah0, p_Al0, 2048, w_ih0, 1536, w_hh0,
                                  b_ih0, b_hh0, p_gpart, 2048, 512);
    k_cell0<<<128, 256>>>(c0, o_h1, o_c1);

    // layer 1 gates: (64,1024) @ [w_ih1|w_hh1]^T, split-K x4
    tc_gemm<<<dim3(32, 4), 256>>>(p_Ah1, p_Al1, 1024, w_ih1, 512, w_hh1,
                                  b_ih1, b_hh1, p_gpart, 2048, 256);
    k_cell1<<<128, 256>>>(c0 + 32768, o_output, o_h2, o_c2);

    // pred: (64,512) @ out_W^T + out_b -> (64, 32000)
    tc_gemm<<<dim3(500, 1), 256>>>(p_Ah2, p_Al2, 512, out_W, 512, nullptr,
                                   out_b, nullptr, o_pred, 32000, 512);
}

// round 5
// speedup vs baseline: 2.2428x; 1.0025x over previous
#include <cuda_runtime.h>
#include <cuda_bf16.h>
#include <math.h>

#define Bsz 64
#define Hs  512
#define Ss  256
#define Vv  32000

// ------------------- scratch (__device__ globals, no allocation) -------------
__device__ float g_edt[Bsz * Ss];            // encdot [b'][s']
__device__ float g_norm[Ss * Bsz];           // normalized [s][b]
__device__ float g_aspart[4 * Bsz * 1024];   // attn_sum split-S partials [sp][b][d]
__device__ float g_gpart[4 * Bsz * 2048];    // split-K partial gates
// bf16 hi/lo activation buffers (GEMM A operands)
__device__ __nv_bfloat16 g_Ah0[Bsz * 2048], g_Al0[Bsz * 2048];  // xcat layer0
__device__ __nv_bfloat16 g_Ah1[Bsz * 1024], g_Al1[Bsz * 1024];  // xcat layer1
__device__ __nv_bfloat16 g_Ah2[Bsz * 512],  g_Al2[Bsz * 512];   // h2

__device__ __forceinline__ void bfsplit(float x, __nv_bfloat16& h, __nv_bfloat16& l) {
    h = __float2bfloat16(x);
    l = __float2bfloat16(x - __bfloat162float(h));
}

// ------------------- attention: encdot[s',b'] = enc[s',b',:] . We ------------
__global__ void k_encdot(const float* __restrict__ enc,
                         const float* __restrict__ attn_W) {
    __shared__ __align__(16) float We[1024];
    for (int i = threadIdx.x; i < 1024; i += blockDim.x) We[i] = attn_W[512 + i];
    __syncthreads();
    int wid  = (blockIdx.x * blockDim.x + threadIdx.x) >> 5;
    int lane = threadIdx.x & 31;
    const float4* e4 = (const float4*)(enc + (size_t)wid * 1024);
    const float4* w4 = (const float4*)We;
    float acc = 0.f;
#pragma unroll
    for (int it = 0; it < 8; it++) {
        float4 a = e4[it * 32 + lane];
        float4 w = w4[it * 32 + lane];
        acc += a.x * w.x + a.y * w.y + a.z * w.z + a.w * w.w;
    }
#pragma unroll
    for (int o = 16; o; o >>= 1) acc += __shfl_xor_sync(0xFFFFFFFFu, acc, o);
    if (lane == 0) {
        int sp = wid >> 6, bp = wid & 63;
        g_edt[bp * 256 + sp] = acc;
    }
}

// ------------------- fused softmax + pack ------------------------------------
// blocks 0..31: softmax (hWh + attn_b cancel). blocks 32..159: pack input/h0.
__global__ void k_softpack(const float* __restrict__ input,
                           const float* __restrict__ h0) {
    if (blockIdx.x < 32) {
        int s    = (blockIdx.x * blockDim.x + threadIdx.x) >> 5;
        int lane = threadIdx.x & 31;
        int base = (s >> 2) * 256 + (s & 3) * 64;
        float v0 = g_edt[base + lane];
        float v1 = g_edt[base + 32 + lane];
        float m = fmaxf(v0, v1);
#pragma unroll
        for (int o = 16; o; o >>= 1) m = fmaxf(m, __shfl_xor_sync(0xFFFFFFFFu, m, o));
        float e0 = expf(v0 - m), e1 = expf(v1 - m);
        float sum = e0 + e1;
#pragma unroll
        for (int o = 16; o; o >>= 1) sum += __shfl_xor_sync(0xFFFFFFFFu, sum, o);
        float inv = 1.f / sum;
        g_norm[s * 64 + lane]      = e0 * inv;
        g_norm[s * 64 + 32 + lane] = e1 * inv;
    } else {
        int i = (blockIdx.x - 32) * blockDim.x + threadIdx.x;   // 0..32767
        int b = i >> 9, j = i & 511;
        __nv_bfloat16 h, l;
        bfsplit(input[i], h, l);
        g_Ah0[b * 2048 + 1024 + j] = h; g_Al0[b * 2048 + 1024 + j] = l;
        bfsplit(h0[i], h, l);
        g_Ah0[b * 2048 + 1536 + j] = h; g_Al0[b * 2048 + 1536 + j] = l;
        bfsplit(h0[32768 + i], h, l);
        g_Ah1[b * 1024 + 512 + j] = h;  g_Al1[b * 1024 + 512 + j] = l;
    }
}

// ------------------- attn_sum split-S partials -------------------------------
__global__ void k_attnsum(const float* __restrict__ enc) {
    int b     = blockIdx.x;        // 0..63
    int chunk = blockIdx.y;        // 0..3
    int sp    = blockIdx.z;        // 0..3 (S split)
    __shared__ float nc[64];
    if (threadIdx.x < 64)
        nc[threadIdx.x] = g_norm[(sp * 64 + threadIdx.x) * 64 + b];
    __syncthreads();
    int d = chunk * 256 + threadIdx.x;
    const float* ep = enc + (size_t)sp * 64 * 65536 + b * 1024 + d;
    float a0 = 0.f, a1 = 0.f, a2 = 0.f, a3 = 0.f;
#pragma unroll 4
    for (int s = 0; s < 64; s += 4) {
        a0 += nc[s]     * ep[(s)     * 65536];
        a1 += nc[s + 1] * ep[(s + 1) * 65536];
        a2 += nc[s + 2] * ep[(s + 2) * 65536];
        a3 += nc[s + 3] * ep[(s + 3) * 65536];
    }
    g_aspart[(sp * 64 + b) * 1024 + d] = (a0 + a1) + (a2 + a3);
}

// ------------------- reduce partials -> xcat[:,0:1024] hi/lo -----------------
__global__ void k_asreduce() {
    int idx = blockIdx.x * blockDim.x + threadIdx.x;   // 0..65535
    int b = idx >> 10, d = idx & 1023;
    float v = g_aspart[b * 1024 + d] + g_aspart[(64 + b) * 1024 + d]
            + g_aspart[(128 + b) * 1024 + d] + g_aspart[(192 + b) * 1024 + d];
    __nv_bfloat16 h, l; bfsplit(v, h, l);
    g_Ah0[b * 2048 + d] = h;
    g_Al0[b * 2048 + d] = l;
}

// ------------------- tensor-core GEMM: out = A(64,K) @ [WA|WB]^T + bias ------
// bf16-split (hi/lo) mma.m16n8k16, fp32 accumulate. 256 threads, tile 64x64,
// warps 2(M)x4(N). Register-staged pipeline hides global load latency.
// Split-K via blockIdx.y (kChunk multiple of 32; chunks never straddle KA).
__device__ __forceinline__ void ldmx4(unsigned* r, unsigned addr) {
    asm volatile("ldmatrix.sync.aligned.m8n8.x4.shared.b16 {%0,%1,%2,%3}, [%4];"
                 : "=r"(r[0]), "=r"(r[1]), "=r"(r[2]), "=r"(r[3]) : "r"(addr));
}
__device__ __forceinline__ void mma16816(float* d, const unsigned* a, const unsigned* b) {
    asm volatile("mma.sync.aligned.m16n8k16.row.col.f32.bf16.bf16.f32 "
                 "{%0,%1,%2,%3},{%4,%5,%6,%7},{%8,%9},{%0,%1,%2,%3};"
                 : "+f"(d[0]), "+f"(d[1]), "+f"(d[2]), "+f"(d[3])
                 : "r"(a[0]), "r"(a[1]), "r"(a[2]), "r"(a[3]), "r"(b[0]), "r"(b[1]));
}

__global__ void __launch_bounds__(256) tc_gemm(
    const __nv_bfloat16* __restrict__ Ah, const __nv_bfloat16* __restrict__ Al, int K,
    const float* __restrict__ WA, int KA, const float* __restrict__ WB,
    const float* __restrict__ bias0, const float* __restrict__ bias1,
    float* __restrict__ out, int N, int kChunk)
{
    __shared__ __align__(16) __nv_bfloat16 sAh[64 * 40], sAl[64 * 40];
    __shared__ __align__(16) __nv_bfloat16 sBh[64 * 40], sBl[64 * 40];
    int tid = threadIdx.x, warp = tid >> 5, lane = tid & 31;
    int warp_m = warp >> 2, warp_n = warp & 3;
    int j0   = blockIdx.x * 64;
    int kidx = blockIdx.y;
    int kbeg = kidx * kChunk, kend = kbeg + kChunk;
    int KB = K - KA;
    float acc[2][2][4] = {};

    // ldmatrix lane->address components
    int a_row = lane & 15;
    int a_k   = (lane >> 4) * 8;
    int b_row = warp_n * 16 + ((lane >> 4) << 3) + (lane & 7);
    int b_k   = ((lane >> 3) & 1) * 8;

    unsigned sAh_b = (unsigned)__cvta_generic_to_shared(sAh);
    unsigned sAl_b = (unsigned)__cvta_generic_to_shared(sAl);
    unsigned sBh_b = (unsigned)__cvta_generic_to_shared(sBh);
    unsigned sBl_b = (unsigned)__cvta_generic_to_shared(sBl);

    // load-index precompute
    int arow = tid >> 2, ac8 = tid & 3;            // A: 64 rows x 4 uint4
    int wrow = tid >> 3, wc4 = tid & 7;            // W: 32 rows x 8 float4 (x2)

    // staging registers
    uint4 rAh, rAl; float4 rW0, rW1;

    auto loadregs = [&](int k0) {
        rAh = *(const uint4*)(Ah + (size_t)arow * K + k0 + ac8 * 8);
        rAl = *(const uint4*)(Al + (size_t)arow * K + k0 + ac8 * 8);
        const float* wp; int ld, kc;
        if (k0 < KA) { wp = WA; ld = KA; kc = k0; }
        else         { wp = WB; ld = KB; kc = k0 - KA; }
        rW0 = *(const float4*)(wp + (size_t)(j0 + wrow) * ld + kc + wc4 * 4);
        rW1 = *(const float4*)(wp + (size_t)(j0 + wrow + 32) * ld + kc + wc4 * 4);
    };
    auto storeregs = [&]() {
        *(uint4*)((char*)sAh + arow * 80 + ac8 * 16) = rAh;
        *(uint4*)((char*)sAl + arow * 80 + ac8 * 16) = rAl;
#pragma unroll
        for (int half = 0; half < 2; half++) {
            float4 v = half ? rW1 : rW0;
            int row = wrow + half * 32;
            __nv_bfloat16 hx, lx, hy, ly, hz, lz, hw, lw;
            bfsplit(v.x, hx, lx); bfsplit(v.y, hy, ly);
            bfsplit(v.z, hz, lz); bfsplit(v.w, hw, lw);
            __nv_bfloat162 H0; H0.x = hx; H0.y = hy;
            __nv_bfloat162 H1; H1.x = hz; H1.y = hw;
            __nv_bfloat162 L0; L0.x = lx; L0.y = ly;
            __nv_bfloat162 L1; L1.x = lz; L1.y = lw;
            char* bh = (char*)sBh + row * 80 + wc4 * 8;
            char* bl = (char*)sBl + row * 80 + wc4 * 8;
            *(__nv_bfloat162*)bh = H0; *(__nv_bfloat162*)(bh + 4) = H1;
            *(__nv_bfloat162*)bl = L0; *(__nv_bfloat162*)(bl + 4) = L1;
        }
    };

    loadregs(kbeg);
    for (int k0 = kbeg; k0 < kend; k0 += 32) {
        storeregs();
        __syncthreads();
        if (k0 + 32 < kend) loadregs(k0 + 32);   // overlap next loads with MMA
#pragma unroll
        for (int kk = 0; kk < 32; kk += 16) {
            unsigned bh[4], bl[4];
            unsigned baddr = (unsigned)(b_row * 80 + (kk + b_k) * 2);
            ldmx4(bh, sBh_b + baddr);
            ldmx4(bl, sBl_b + baddr);
#pragma unroll
            for (int mi = 0; mi < 2; mi++) {
                unsigned ah[4], al[4];
                int grow = warp_m * 32 + mi * 16 + a_row;
                unsigned aaddr = (unsigned)(grow * 80 + (kk + a_k) * 2);
                ldmx4(ah, sAh_b + aaddr);
                ldmx4(al, sAl_b + aaddr);
                mma16816(acc[mi][0], ah, &bh[0]);
                mma16816(acc[mi][0], ah, &bl[0]);
                mma16816(acc[mi][0], al, &bh[0]);
                mma16816(acc[mi][1], ah, &bh[2]);
                mma16816(acc[mi][1], ah, &bl[2]);
                mma16816(acc[mi][1], al, &bh[2]);
            }
        }
        __syncthreads();
    }

    int orow = lane >> 2;
    int ocol = (lane & 3) * 2;
    float* op = out + (size_t)kidx * 64 * N;
#pragma unroll
    for (int mi = 0; mi < 2; mi++) {
#pragma unroll
        for (int nj = 0; nj < 2; nj++) {
            int col = j0 + warp_n * 16 + nj * 8 + ocol;
            float bA = 0.f, bB = 0.f;
            if (kidx == 0) {
                if (bias0) { bA += bias0[col]; bB += bias0[col + 1]; }
                if (bias1) { bA += bias1[col]; bB += bias1[col + 1]; }
            }
            int r0 = warp_m * 32 + mi * 16 + orow;
            op[(size_t)r0 * N + col]           = acc[mi][nj][0] + bA;
            op[(size_t)r0 * N + col + 1]       = acc[mi][nj][1] + bB;
            op[(size_t)(r0 + 8) * N + col]     = acc[mi][nj][2] + bA;
            op[(size_t)(r0 + 8) * N + col + 1] = acc[mi][nj][3] + bB;
        }
    }
}

// ------------------- LSTM cell epilogues (sum split-K parts) -----------------
__device__ __forceinline__ float sigf(float x) { return 1.f / (1.f + expf(-x)); }

__global__ void k_cell0(const float* __restrict__ c0,
                        float* __restrict__ h_out,
                        float* __restrict__ c_out) {
    int idx = blockIdx.x * blockDim.x + threadIdx.x;
    int b = idx >> 9, j = idx & 511;
    int base = b * 2048;
    float gi = 0, gf = 0, gg = 0, go = 0;
#pragma unroll
    for (int p = 0; p < 4; p++) {
        const float* gp = g_gpart + p * 64 * 2048 + base;
        gi += gp[j]; gf += gp[512 + j]; gg += gp[1024 + j]; go += gp[1536 + j];
    }
    float c = sigf(gf) * c0[idx] + sigf(gi) * tanhf(gg);
    float h = sigf(go) * tanhf(c);
    h_out[idx] = h;
    c_out[idx] = c;
    __nv_bfloat16 hh, ll; bfsplit(h, hh, ll);
    g_Ah1[b * 1024 + j] = hh;
    g_Al1[b * 1024 + j] = ll;
}

__global__ void k_cell1(const float* __restrict__ c0b,
                        float* __restrict__ out0,
                        float* __restrict__ h_out,
                        float* __restrict__ c_out) {
    int idx = blockIdx.x * blockDim.x + threadIdx.x;
    int b = idx >> 9, j = idx & 511;
    int base = b * 2048;
    float gi = 0, gf = 0, gg = 0, go = 0;
#pragma unroll
    for (int p = 0; p < 4; p++) {
        const float* gp = g_gpart + p * 64 * 2048 + base;
        gi += gp[j]; gf += gp[512 + j]; gg += gp[1024 + j]; go += gp[1536 + j];
    }
    float c = sigf(gf) * c0b[idx] + sigf(gi) * tanhf(gg);
    float h = sigf(go) * tanhf(c);
    out0[idx]  = h;
    h_out[idx] = h;
    c_out[idx] = c;
    __nv_bfloat16 hh, ll; bfsplit(h, hh, ll);
    g_Ah2[idx] = hh;
    g_Al2[idx] = ll;
}

// ------------------- launch ---------------------------------------------------
extern "C" void kernel_launch(void* const* d_in, const int* in_sizes, int n_in,
                              void* d_out, int out_size) {
    const float* input = (const float*)d_in[0];
    const float* h0    = (const float*)d_in[1];
    const float* c0    = (const float*)d_in[2];
    const float* enc   = (const float*)d_in[3];
    const float* attnW = (const float*)d_in[4];
    const float* w_ih0 = (const float*)d_in[6];
    const float* w_hh0 = (const float*)d_in[7];
    const float* b_ih0 = (const float*)d_in[8];
    const float* b_hh0 = (const float*)d_in[9];
    const float* w_ih1 = (const float*)d_in[10];
    const float* w_hh1 = (const float*)d_in[11];
    const float* b_ih1 = (const float*)d_in[12];
    const float* b_hh1 = (const float*)d_in[13];
    const float* out_W = (const float*)d_in[14];
    const float* out_b = (const float*)d_in[15];
    float* out = (float*)d_out;

    float* p_gpart;
    __nv_bfloat16 *p_Ah0, *p_Al0, *p_Ah1, *p_Al1, *p_Ah2, *p_Al2;
    cudaGetSymbolAddress((void**)&p_gpart, g_gpart);
    cudaGetSymbolAddress((void**)&p_Ah0, g_Ah0);
    cudaGetSymbolAddress((void**)&p_Al0, g_Al0);
    cudaGetSymbolAddress((void**)&p_Ah1, g_Ah1);
    cudaGetSymbolAddress((void**)&p_Al1, g_Al1);
    cudaGetSymbolAddress((void**)&p_Ah2, g_Ah2);
    cudaGetSymbolAddress((void**)&p_Al2, g_Al2);

    // Output layout: [output | h_new | c_new | pred]
    float* o_output = out;
    float* o_h1 = out + 32768;
    float* o_h2 = out + 65536;
    float* o_c1 = out + 98304;
    float* o_c2 = out + 131072;
    float* o_pred = out + 163840;

    k_encdot<<<2048, 256>>>(enc, attnW);
    k_softpack<<<160, 256>>>(input, h0);
    k_attnsum<<<dim3(64, 4, 4), 256>>>(enc);
    k_asreduce<<<256, 256>>>();

    // layer 0 gates: (64,2048) @ [w_ih0|w_hh0]^T, split-K x4
    tc_gemm<<<dim3(32, 4), 256>>>(p_Ah0, p_Al0, 2048, w_ih0, 1536, w_hh0,
                                  b_ih0, b_hh0, p_gpart, 2048, 512);
    k_cell0<<<128, 256>>>(c0, o_h1, o_c1);

    // layer 1 gates: (64,1024) @ [w_ih1|w_hh1]^T, split-K x4
    tc_gemm<<<dim3(32, 4), 256>>>(p_Ah1, p_Al1, 1024, w_ih1, 512, w_hh1,
                                  b_ih1, b_hh1, p_gpart, 2048, 256);
    k_cell1<<<128, 256>>>(c0 + 32768, o_output, o_h2, o_c2);

    // pred: (64,512) @ out_W^T + out_b -> (64, 32000)
    tc_gemm<<<dim3(500, 1), 256>>>(p_Ah2, p_Al2, 512, out_W, 512, nullptr,
                                   out_b, nullptr, o_pred, 32000, 512);
}

// round 6
// speedup vs baseline: 2.2471x; 1.0019x over previous
#include <cuda_runtime.h>
#include <cuda_bf16.h>
#include <math.h>

#define Bsz 64
#define Hs  512
#define Ss  256
#define Vv  32000

// ------------------- scratch (__device__ globals, no allocation) -------------
__device__ float g_edt[Bsz * Ss];            // encdot [b'][s']
__device__ float g_norm[Ss * Bsz];           // normalized [s][b]
__device__ float g_aspart[4 * Bsz * 1024];   // attn_sum split-S partials [sp][b][d]
__device__ float g_gpart[4 * Bsz * 2048];    // split-K partial gates
// bf16 hi/lo activation buffers (GEMM A operands)
__device__ __nv_bfloat16 g_Ah0[Bsz * 2048], g_Al0[Bsz * 2048];  // xcat layer0
__device__ __nv_bfloat16 g_Ah1[Bsz * 1024], g_Al1[Bsz * 1024];  // xcat layer1
__device__ __nv_bfloat16 g_Ah2[Bsz * 512],  g_Al2[Bsz * 512];   // h2

__device__ __forceinline__ void bfsplit(float x, __nv_bfloat16& h, __nv_bfloat16& l) {
    h = __float2bfloat16(x);
    l = __float2bfloat16(x - __bfloat162float(h));
}

// ------------------- attention: encdot[s',b'] = enc[s',b',:] . We ------------
__global__ void k_encdot(const float* __restrict__ enc,
                         const float* __restrict__ attn_W) {
    __shared__ __align__(16) float We[1024];
    for (int i = threadIdx.x; i < 1024; i += blockDim.x) We[i] = attn_W[512 + i];
    __syncthreads();
    int wid  = (blockIdx.x * blockDim.x + threadIdx.x) >> 5;
    int lane = threadIdx.x & 31;
    const float4* e4 = (const float4*)(enc + (size_t)wid * 1024);
    const float4* w4 = (const float4*)We;
    float acc = 0.f;
#pragma unroll
    for (int it = 0; it < 8; it++) {
        float4 a = e4[it * 32 + lane];
        float4 w = w4[it * 32 + lane];
        acc += a.x * w.x + a.y * w.y + a.z * w.z + a.w * w.w;
    }
#pragma unroll
    for (int o = 16; o; o >>= 1) acc += __shfl_xor_sync(0xFFFFFFFFu, acc, o);
    if (lane == 0) {
        int sp = wid >> 6, bp = wid & 63;
        g_edt[bp * 256 + sp] = acc;
    }
}

// ------------------- fused softmax + pack ------------------------------------
// blocks 0..31: softmax (hWh + attn_b cancel). blocks 32..159: pack input/h0.
__global__ void k_softpack(const float* __restrict__ input,
                           const float* __restrict__ h0) {
    if (blockIdx.x < 32) {
        int s    = (blockIdx.x * blockDim.x + threadIdx.x) >> 5;
        int lane = threadIdx.x & 31;
        int base = (s >> 2) * 256 + (s & 3) * 64;
        float v0 = g_edt[base + lane];
        float v1 = g_edt[base + 32 + lane];
        float m = fmaxf(v0, v1);
#pragma unroll
        for (int o = 16; o; o >>= 1) m = fmaxf(m, __shfl_xor_sync(0xFFFFFFFFu, m, o));
        float e0 = expf(v0 - m), e1 = expf(v1 - m);
        float sum = e0 + e1;
#pragma unroll
        for (int o = 16; o; o >>= 1) sum += __shfl_xor_sync(0xFFFFFFFFu, sum, o);
        float inv = 1.f / sum;
        g_norm[s * 64 + lane]      = e0 * inv;
        g_norm[s * 64 + 32 + lane] = e1 * inv;
    } else {
        int i = (blockIdx.x - 32) * blockDim.x + threadIdx.x;   // 0..32767
        int b = i >> 9, j = i & 511;
        __nv_bfloat16 h, l;
        bfsplit(input[i], h, l);
        g_Ah0[b * 2048 + 1024 + j] = h; g_Al0[b * 2048 + 1024 + j] = l;
        bfsplit(h0[i], h, l);
        g_Ah0[b * 2048 + 1536 + j] = h; g_Al0[b * 2048 + 1536 + j] = l;
        bfsplit(h0[32768 + i], h, l);
        g_Ah1[b * 1024 + 512 + j] = h;  g_Al1[b * 1024 + 512 + j] = l;
    }
}

// ------------------- attn_sum split-S partials -------------------------------
__global__ void k_attnsum(const float* __restrict__ enc) {
    int b     = blockIdx.x;        // 0..63
    int chunk = blockIdx.y;        // 0..3
    int sp    = blockIdx.z;        // 0..3 (S split)
    __shared__ float nc[64];
    if (threadIdx.x < 64)
        nc[threadIdx.x] = g_norm[(sp * 64 + threadIdx.x) * 64 + b];
    __syncthreads();
    int d = chunk * 256 + threadIdx.x;
    const float* ep = enc + (size_t)sp * 64 * 65536 + b * 1024 + d;
    float a0 = 0.f, a1 = 0.f, a2 = 0.f, a3 = 0.f;
#pragma unroll 4
    for (int s = 0; s < 64; s += 4) {
        a0 += nc[s]     * ep[(s)     * 65536];
        a1 += nc[s + 1] * ep[(s + 1) * 65536];
        a2 += nc[s + 2] * ep[(s + 2) * 65536];
        a3 += nc[s + 3] * ep[(s + 3) * 65536];
    }
    g_aspart[(sp * 64 + b) * 1024 + d] = (a0 + a1) + (a2 + a3);
}

// ------------------- reduce partials -> xcat[:,0:1024] hi/lo -----------------
__global__ void k_asreduce() {
    int idx = blockIdx.x * blockDim.x + threadIdx.x;   // 0..65535
    int b = idx >> 10, d = idx & 1023;
    float v = g_aspart[b * 1024 + d] + g_aspart[(64 + b) * 1024 + d]
            + g_aspart[(128 + b) * 1024 + d] + g_aspart[(192 + b) * 1024 + d];
    __nv_bfloat16 h, l; bfsplit(v, h, l);
    g_Ah0[b * 2048 + d] = h;
    g_Al0[b * 2048 + d] = l;
}

// ------------------- tensor-core GEMM: out = A(64,K) @ [WA|WB]^T + bias ------
// bf16-split (hi/lo) mma.m16n8k16, fp32 accumulate. 256 threads, tile 64x64,
// warps 2(M)x4(N). Register-staged pipeline hides global load latency.
// Split-K via blockIdx.y (kChunk multiple of 32; chunks never straddle KA).
__device__ __forceinline__ void ldmx4(unsigned* r, unsigned addr) {
    asm volatile("ldmatrix.sync.aligned.m8n8.x4.shared.b16 {%0,%1,%2,%3}, [%4];"
                 : "=r"(r[0]), "=r"(r[1]), "=r"(r[2]), "=r"(r[3]) : "r"(addr));
}
__device__ __forceinline__ void mma16816(float* d, const unsigned* a, const unsigned* b) {
    asm volatile("mma.sync.aligned.m16n8k16.row.col.f32.bf16.bf16.f32 "
                 "{%0,%1,%2,%3},{%4,%5,%6,%7},{%8,%9},{%0,%1,%2,%3};"
                 : "+f"(d[0]), "+f"(d[1]), "+f"(d[2]), "+f"(d[3])
                 : "r"(a[0]), "r"(a[1]), "r"(a[2]), "r"(a[3]), "r"(b[0]), "r"(b[1]));
}

__global__ void __launch_bounds__(256) tc_gemm(
    const __nv_bfloat16* __restrict__ Ah, const __nv_bfloat16* __restrict__ Al, int K,
    const float* __restrict__ WA, int KA, const float* __restrict__ WB,
    const float* __restrict__ bias0, const float* __restrict__ bias1,
    float* __restrict__ out, int N, int kChunk)
{
    __shared__ __align__(16) __nv_bfloat16 sAh[64 * 40], sAl[64 * 40];
    __shared__ __align__(16) __nv_bfloat16 sBh[64 * 40], sBl[64 * 40];
    int tid = threadIdx.x, warp = tid >> 5, lane = tid & 31;
    int warp_m = warp >> 2, warp_n = warp & 3;
    int j0   = blockIdx.x * 64;
    int kidx = blockIdx.y;
    int kbeg = kidx * kChunk, kend = kbeg + kChunk;
    int KB = K - KA;
    float acc[2][2][4] = {};

    // ldmatrix lane->address components
    int a_row = lane & 15;
    int a_k   = (lane >> 4) * 8;
    int b_row = warp_n * 16 + ((lane >> 4) << 3) + (lane & 7);
    int b_k   = ((lane >> 3) & 1) * 8;

    unsigned sAh_b = (unsigned)__cvta_generic_to_shared(sAh);
    unsigned sAl_b = (unsigned)__cvta_generic_to_shared(sAl);
    unsigned sBh_b = (unsigned)__cvta_generic_to_shared(sBh);
    unsigned sBl_b = (unsigned)__cvta_generic_to_shared(sBl);

    // load-index precompute
    int arow = tid >> 2, ac8 = tid & 3;            // A: 64 rows x 4 uint4
    int wrow = tid >> 3, wc4 = tid & 7;            // W: 32 rows x 8 float4 (x2)

    // staging registers
    uint4 rAh, rAl; float4 rW0, rW1;

    auto loadregs = [&](int k0) {
        rAh = *(const uint4*)(Ah + (size_t)arow * K + k0 + ac8 * 8);
        rAl = *(const uint4*)(Al + (size_t)arow * K + k0 + ac8 * 8);
        const float* wp; int ld, kc;
        if (k0 < KA) { wp = WA; ld = KA; kc = k0; }
        else         { wp = WB; ld = KB; kc = k0 - KA; }
        rW0 = *(const float4*)(wp + (size_t)(j0 + wrow) * ld + kc + wc4 * 4);
        rW1 = *(const float4*)(wp + (size_t)(j0 + wrow + 32) * ld + kc + wc4 * 4);
    };
    auto storeregs = [&]() {
        *(uint4*)((char*)sAh + arow * 80 + ac8 * 16) = rAh;
        *(uint4*)((char*)sAl + arow * 80 + ac8 * 16) = rAl;
#pragma unroll
        for (int half = 0; half < 2; half++) {
            float4 v = half ? rW1 : rW0;
            int row = wrow + half * 32;
            __nv_bfloat16 hx, lx, hy, ly, hz, lz, hw, lw;
            bfsplit(v.x, hx, lx); bfsplit(v.y, hy, ly);
            bfsplit(v.z, hz, lz); bfsplit(v.w, hw, lw);
            __nv_bfloat162 H0; H0.x = hx; H0.y = hy;
            __nv_bfloat162 H1; H1.x = hz; H1.y = hw;
            __nv_bfloat162 L0; L0.x = lx; L0.y = ly;
            __nv_bfloat162 L1; L1.x = lz; L1.y = lw;
            char* bh = (char*)sBh + row * 80 + wc4 * 8;
            char* bl = (char*)sBl + row * 80 + wc4 * 8;
            *(__nv_bfloat162*)bh = H0; *(__nv_bfloat162*)(bh + 4) = H1;
            *(__nv_bfloat162*)bl = L0; *(__nv_bfloat162*)(bl + 4) = L1;
        }
    };

    loadregs(kbeg);
    for (int k0 = kbeg; k0 < kend; k0 += 32) {
        storeregs();
        __syncthreads();
        if (k0 + 32 < kend) loadregs(k0 + 32);   // overlap next loads with MMA
#pragma unroll
        for (int kk = 0; kk < 32; kk += 16) {
            unsigned bh[4], bl[4];
            unsigned baddr = (unsigned)(b_row * 80 + (kk + b_k) * 2);
            ldmx4(bh, sBh_b + baddr);
            ldmx4(bl, sBl_b + baddr);
#pragma unroll
            for (int mi = 0; mi < 2; mi++) {
                unsigned ah[4], al[4];
                int grow = warp_m * 32 + mi * 16 + a_row;
                unsigned aaddr = (unsigned)(grow * 80 + (kk + a_k) * 2);
                ldmx4(ah, sAh_b + aaddr);
                ldmx4(al, sAl_b + aaddr);
                mma16816(acc[mi][0], ah, &bh[0]);
                mma16816(acc[mi][0], ah, &bl[0]);
                mma16816(acc[mi][0], al, &bh[0]);
                mma16816(acc[mi][1], ah, &bh[2]);
                mma16816(acc[mi][1], ah, &bl[2]);
                mma16816(acc[mi][1], al, &bh[2]);
            }
        }
        __syncthreads();
    }

    int orow = lane >> 2;
    int ocol = (lane & 3) * 2;
    float* op = out + (size_t)kidx * 64 * N;
#pragma unroll
    for (int mi = 0; mi < 2; mi++) {
#pragma unroll
        for (int nj = 0; nj < 2; nj++) {
            int col = j0 + warp_n * 16 + nj * 8 + ocol;
            float bA = 0.f, bB = 0.f;
            if (kidx == 0) {
                if (bias0) { bA += bias0[col]; bB += bias0[col + 1]; }
                if (bias1) { bA += bias1[col]; bB += bias1[col + 1]; }
            }
            int r0 = warp_m * 32 + mi * 16 + orow;
            op[(size_t)r0 * N + col]           = acc[mi][nj][0] + bA;
            op[(size_t)r0 * N + col + 1]       = acc[mi][nj][1] + bB;
            op[(size_t)(r0 + 8) * N + col]     = acc[mi][nj][2] + bA;
            op[(size_t)(r0 + 8) * N + col + 1] = acc[mi][nj][3] + bB;
        }
    }
}

// ------------------- LSTM cell epilogues (sum split-K parts) -----------------
__device__ __forceinline__ float sigf(float x) { return 1.f / (1.f + expf(-x)); }

__global__ void k_cell0(const float* __restrict__ c0,
                        float* __restrict__ h_out,
                        float* __restrict__ c_out) {
    int idx = blockIdx.x * blockDim.x + threadIdx.x;
    int b = idx >> 9, j = idx & 511;
    int base = b * 2048;
    float gi = 0, gf = 0, gg = 0, go = 0;
#pragma unroll
    for (int p = 0; p < 4; p++) {
        const float* gp = g_gpart + p * 64 * 2048 + base;
        gi += gp[j]; gf += gp[512 + j]; gg += gp[1024 + j]; go += gp[1536 + j];
    }
    float c = sigf(gf) * c0[idx] + sigf(gi) * tanhf(gg);
    float h = sigf(go) * tanhf(c);
    h_out[idx] = h;
    c_out[idx] = c;
    __nv_bfloat16 hh, ll; bfsplit(h, hh, ll);
    g_Ah1[b * 1024 + j] = hh;
    g_Al1[b * 1024 + j] = ll;
}

__global__ void k_cell1(const float* __restrict__ c0b,
                        float* __restrict__ out0,
                        float* __restrict__ h_out,
                        float* __restrict__ c_out) {
    int idx = blockIdx.x * blockDim.x + threadIdx.x;
    int b = idx >> 9, j = idx & 511;
    int base = b * 2048;
    float gi = 0, gf = 0, gg = 0, go = 0;
#pragma unroll
    for (int p = 0; p < 4; p++) {
        const float* gp = g_gpart + p * 64 * 2048 + base;
        gi += gp[j]; gf += gp[512 + j]; gg += gp[1024 + j]; go += gp[1536 + j];
    }
    float c = sigf(gf) * c0b[idx] + sigf(gi) * tanhf(gg);
    float h = sigf(go) * tanhf(c);
    out0[idx]  = h;
    h_out[idx] = h;
    c_out[idx] = c;
    __nv_bfloat16 hh, ll; bfsplit(h, hh, ll);
    g_Ah2[idx] = hh;
    g_Al2[idx] = ll;
}

// ------------------- launch ---------------------------------------------------
extern "C" void kernel_launch(void* const* d_in, const int* in_sizes, int n_in,
                              void* d_out, int out_size) {
    const float* input = (const float*)d_in[0];
    const float* h0    = (const float*)d_in[1];
    const float* c0    = (const float*)d_in[2];
    const float* enc   = (const float*)d_in[3];
    const float* attnW = (const float*)d_in[4];
    const float* w_ih0 = (const float*)d_in[6];
    const float* w_hh0 = (const float*)d_in[7];
    const float* b_ih0 = (const float*)d_in[8];
    const float* b_hh0 = (const float*)d_in[9];
    const float* w_ih1 = (const float*)d_in[10];
    const float* w_hh1 = (const float*)d_in[11];
    const float* b_ih1 = (const float*)d_in[12];
    const float* b_hh1 = (const float*)d_in[13];
    const float* out_W = (const float*)d_in[14];
    const float* out_b = (const float*)d_in[15];
    float* out = (float*)d_out;

    float* p_gpart;
    __nv_bfloat16 *p_Ah0, *p_Al0, *p_Ah1, *p_Al1, *p_Ah2, *p_Al2;
    cudaGetSymbolAddress((void**)&p_gpart, g_gpart);
    cudaGetSymbolAddress((void**)&p_Ah0, g_Ah0);
    cudaGetSymbolAddress((void**)&p_Al0, g_Al0);
    cudaGetSymbolAddress((void**)&p_Ah1, g_Ah1);
    cudaGetSymbolAddress((void**)&p_Al1, g_Al1);
    cudaGetSymbolAddress((void**)&p_Ah2, g_Ah2);
    cudaGetSymbolAddress((void**)&p_Al2, g_Al2);

    // Output layout: [output | h_new | c_new | pred]
    float* o_output = out;
    float* o_h1 = out + 32768;
    float* o_h2 = out + 65536;
    float* o_c1 = out + 98304;
    float* o_c2 = out + 131072;
    float* o_pred = out + 163840;

    k_encdot<<<2048, 256>>>(enc, attnW);
    k_softpack<<<160, 256>>>(input, h0);
    k_attnsum<<<dim3(64, 4, 4), 256>>>(enc);
    k_asreduce<<<256, 256>>>();

    // layer 0 gates: (64,2048) @ [w_ih0|w_hh0]^T, split-K x4
    tc_gemm<<<dim3(32, 4), 256>>>(p_Ah0, p_Al0, 2048, w_ih0, 1536, w_hh0,
                                  b_ih0, b_hh0, p_gpart, 2048, 512);
    k_cell0<<<128, 256>>>(c0, o_h1, o_c1);

    // layer 1 gates: (64,1024) @ [w_ih1|w_hh1]^T, split-K x4
    tc_gemm<<<dim3(32, 4), 256>>>(p_Ah1, p_Al1, 1024, w_ih1, 512, w_hh1,
                                  b_ih1, b_hh1, p_gpart, 2048, 256);
    k_cell1<<<128, 256>>>(c0 + 32768, o_output, o_h2, o_c2);

    // pred: (64,512) @ out_W^T + out_b -> (64, 32000)
    tc_gemm<<<dim3(500, 1), 256>>>(p_Ah2, p_Al2, 512, out_W, 512, nullptr,
                                   out_b, nullptr, o_pred, 32000, 512);
}